// round 5
// baseline (speedup 1.0000x reference)
#include <cuda_runtime.h>

#define BATCH 4
#define SEQ   2048
#define DMODEL 256
#define NHEAD 4
#define HDIM  64
#define BHTOT (BATCH*NHEAD)   // 16

typedef unsigned long long ull;

// Scratch: Q and K transposed [bh][d][s]; V natural [bh][s][d].
__device__ float g_Qt[BHTOT * HDIM * SEQ];
__device__ float g_Kt[BHTOT * HDIM * SEQ];
__device__ float g_V [BHTOT * SEQ * HDIM];

// ---------------- packed f32x2 helpers ----------------
__device__ __forceinline__ void ffma2(ull& d, ull a, ull b) {
    asm("fma.rn.f32x2 %0, %1, %2, %0;" : "+l"(d) : "l"(a), "l"(b));
}
__device__ __forceinline__ ull mul2(ull a, ull b) {
    ull r; asm("mul.rn.f32x2 %0, %1, %2;" : "=l"(r) : "l"(a), "l"(b)); return r;
}
__device__ __forceinline__ ull dup2(float v) {
    ull r; asm("mov.b64 %0, {%1, %1};" : "=l"(r) : "f"(v)); return r;
}
__device__ __forceinline__ ull pack2(float x, float y) {
    ull r; asm("mov.b64 %0, {%1, %2};" : "=l"(r) : "f"(x), "f"(y)); return r;
}
__device__ __forceinline__ float ex2(float x) {
    float r; asm("ex2.approx.ftz.f32 %0, %1;" : "=f"(r) : "f"(x)); return r;
}

union F2U { float2 f; ull u; };

// ---------------------------------------------------------------------------
// Kernel 1: fused QKV projection (unchanged from passing baseline).
// ---------------------------------------------------------------------------
__global__ __launch_bounds__(256)
void qkv_gemm_kernel(const float* __restrict__ x,
                     const float* __restrict__ W,
                     const float* __restrict__ bias)
{
    __shared__ float Xs[128][32];
    __shared__ float Ws[64][33];

    const int tid = threadIdx.x;
    const int tx = tid & 15;
    const int ty = tid >> 4;
    const int m0 = blockIdx.y * 128;
    const int n0 = blockIdx.x * 64;

    float acc[8][4];
#pragma unroll
    for (int i = 0; i < 8; i++)
#pragma unroll
        for (int j = 0; j < 4; j++) acc[i][j] = 0.f;

    for (int k0 = 0; k0 < DMODEL; k0 += 32) {
#pragma unroll
        for (int e = 0; e < 4; e++) {
            int f  = tid + e * 256;
            int m  = f >> 3;
            int k4 = (f & 7) << 2;
            float4 v = *(const float4*)&x[(m0 + m) * DMODEL + k0 + k4];
            *(float4*)&Xs[m][k4] = v;
        }
#pragma unroll
        for (int e = 0; e < 2; e++) {
            int f  = tid + e * 256;
            int n  = f >> 3;
            int k4 = (f & 7) << 2;
            float4 v = *(const float4*)&W[(n0 + n) * DMODEL + k0 + k4];
            Ws[n][k4 + 0] = v.x; Ws[n][k4 + 1] = v.y;
            Ws[n][k4 + 2] = v.z; Ws[n][k4 + 3] = v.w;
        }
        __syncthreads();

#pragma unroll
        for (int kk = 0; kk < 32; kk++) {
            float a[8], b[4];
#pragma unroll
            for (int i = 0; i < 8; i++) a[i] = Xs[ty * 8 + i][kk];
#pragma unroll
            for (int j = 0; j < 4; j++) b[j] = Ws[tx * 4 + j][kk];
#pragma unroll
            for (int i = 0; i < 8; i++)
#pragma unroll
                for (int j = 0; j < 4; j++)
                    acc[i][j] += a[i] * b[j];
        }
        __syncthreads();
    }

    float bj[4];
#pragma unroll
    for (int j = 0; j < 4; j++) bj[j] = bias[n0 + tx * 4 + j];

#pragma unroll
    for (int i = 0; i < 8; i++) {
        int m = m0 + ty * 8 + i;
        int b_idx = m >> 11;
        int s     = m & (SEQ - 1);
#pragma unroll
        for (int j = 0; j < 4; j++) {
            int e = n0 + tx * 4 + j;
            float v = acc[i][j] + bj[j];
            int which = e >> 8;
            int rem   = e & 255;
            int h     = rem >> 6;
            int dh    = rem & 63;
            int bh    = b_idx * NHEAD + h;
            if (which == 0)
                g_Qt[(bh * HDIM + dh) * SEQ + s] = v;
            else if (which == 1)
                g_Kt[(bh * HDIM + dh) * SEQ + s] = v;
            else
                g_V[(bh * SEQ + s) * HDIM + dh] = v;
        }
    }
}

// ---------------------------------------------------------------------------
// Kernel 2: flash attention with packed f32x2 FMA.
// Accumulators pair adjacent query rows: acc[i2][j] = (row 2*i2, row 2*i2+1).
// K and V live in smem duplicated+swizzled so (k,k) pairs load as one LDS.64
// conflict-free:  pos(c) = 8*tx + 2*(tx>>2) + 2*j  for c = tx*4+j.
// P stored transposed Pt[kcol][qrow] via STS.64 of the row-pairs; aliases Ktd.
// smem: Qts 64*128 (32KB) | union(Ktd 64*136, Pt 64*130) (34KB) | Vsd 64*136 (34KB)
// ---------------------------------------------------------------------------
#define KROW 136
#define PROW 130
#define QS   (0.125f * 1.44269504088896340736f)   // scale * log2(e)

__global__ __launch_bounds__(256, 2)
void attn_kernel(float* __restrict__ out)
{
    extern __shared__ float sm[];
    float* Qts  = sm;                     // [64][128]
    float* KtPt = Qts + 64 * 128;         // union: Ktd [64][KROW] / Pt [64][PROW]
    float* Vsd  = KtPt + 64 * KROW;       // [64][KROW]

    const int tid = threadIdx.x;
    const int tx = tid & 15;
    const int ty = tid >> 4;
    const int bh = blockIdx.y;
    const int q0 = blockIdx.x * 128;
    const int Bk = 8 * tx + 2 * (tx >> 2);   // swizzled dup-pair base

    const float* Qtg = g_Qt + bh * HDIM * SEQ;
    const float* Ktg = g_Kt + bh * HDIM * SEQ;
    const float* Vg  = g_V  + bh * SEQ * HDIM;

    // Q tile, pre-scaled into log2 domain
#pragma unroll
    for (int e = 0; e < 8; e++) {
        int f  = tid + e * 256;
        int d  = f >> 5;
        int r4 = (f & 31) << 2;
        float4 v = *(const float4*)&Qtg[d * SEQ + q0 + r4];
        v.x *= QS; v.y *= QS; v.z *= QS; v.w *= QS;
        *(float4*)&Qts[d * 128 + r4] = v;
    }

    float m_i[8], l_i[8];
    F2U o[4][4];
#pragma unroll
    for (int r = 0; r < 8; r++) { m_i[r] = -1e30f; l_i[r] = 0.f; }
#pragma unroll
    for (int i2 = 0; i2 < 4; i2++)
#pragma unroll
        for (int j = 0; j < 4; j++) o[i2][j].u = 0ull;

    for (int k0 = 0; k0 < SEQ; k0 += 64) {
        __syncthreads();   // A: prev PV done reading Pt(union) & Vsd

        // K tile -> duplicated swizzled smem (Ktd)
#pragma unroll
        for (int e = 0; e < 4; e++) {
            int f  = tid + e * 256;
            int d  = f >> 4;
            int c4 = (f & 15) << 2;
            float4 kv = *(const float4*)&Ktg[d * SEQ + k0 + c4];
            int base = d * KROW + 2 * c4 + 2 * (c4 >> 4);
            *(ull*)&KtPt[base + 0] = dup2(kv.x);
            *(ull*)&KtPt[base + 2] = dup2(kv.y);
            *(ull*)&KtPt[base + 4] = dup2(kv.z);
            *(ull*)&KtPt[base + 6] = dup2(kv.w);
        }
        // V tile -> duplicated swizzled smem (Vsd)
#pragma unroll
        for (int e = 0; e < 4; e++) {
            int f  = tid + e * 256;
            int k  = f >> 4;
            int c4 = (f & 15) << 2;
            float4 vv = *(const float4*)&Vg[(k0 + k) * HDIM + c4];
            int base = k * KROW + 2 * c4 + 2 * (c4 >> 4);
            *(ull*)&Vsd[base + 0] = dup2(vv.x);
            *(ull*)&Vsd[base + 2] = dup2(vv.y);
            *(ull*)&Vsd[base + 4] = dup2(vv.z);
            *(ull*)&Vsd[base + 6] = dup2(vv.w);
        }
        __syncthreads();   // B: tiles ready

        // S = Q K^T, row-pair accumulators (log2 domain, pre-scaled)
        F2U acc[4][4];
#pragma unroll
        for (int i2 = 0; i2 < 4; i2++)
#pragma unroll
            for (int j = 0; j < 4; j++) acc[i2][j].u = 0ull;

#pragma unroll 8
        for (int d = 0; d < 64; d++) {
            ulonglong2 qA = *(const ulonglong2*)&Qts[d * 128 + ty * 8];
            ulonglong2 qB = *(const ulonglong2*)&Qts[d * 128 + ty * 8 + 4];
            ull qp[4] = {qA.x, qA.y, qB.x, qB.y};
#pragma unroll
            for (int j = 0; j < 4; j++) {
                ull kd = *(const ull*)&KtPt[d * KROW + Bk + 2 * j];
#pragma unroll
                for (int i2 = 0; i2 < 4; i2++)
                    ffma2(acc[i2][j].u, qp[i2], kd);
            }
        }

        // online softmax (base 2), two rows per i2
#pragma unroll
        for (int i2 = 0; i2 < 4; i2++) {
            float mx = fmaxf(fmaxf(acc[i2][0].f.x, acc[i2][1].f.x),
                             fmaxf(acc[i2][2].f.x, acc[i2][3].f.x));
            float my = fmaxf(fmaxf(acc[i2][0].f.y, acc[i2][1].f.y),
                             fmaxf(acc[i2][2].f.y, acc[i2][3].f.y));
#pragma unroll
            for (int off = 8; off > 0; off >>= 1) {
                mx = fmaxf(mx, __shfl_xor_sync(0xffffffffu, mx, off, 16));
                my = fmaxf(my, __shfl_xor_sync(0xffffffffu, my, off, 16));
            }
            float nmx = fmaxf(m_i[2 * i2],     mx);
            float nmy = fmaxf(m_i[2 * i2 + 1], my);
            float ax = ex2(m_i[2 * i2]     - nmx);
            float ay = ex2(m_i[2 * i2 + 1] - nmy);
            m_i[2 * i2] = nmx; m_i[2 * i2 + 1] = nmy;

            float rx = 0.f, ry = 0.f;
#pragma unroll
            for (int j = 0; j < 4; j++) {
                float px = ex2(acc[i2][j].f.x - nmx);
                float py = ex2(acc[i2][j].f.y - nmy);
                acc[i2][j].f.x = px; acc[i2][j].f.y = py;
                rx += px; ry += py;
            }
#pragma unroll
            for (int off = 8; off > 0; off >>= 1) {
                rx += __shfl_xor_sync(0xffffffffu, rx, off, 16);
                ry += __shfl_xor_sync(0xffffffffu, ry, off, 16);
            }
            l_i[2 * i2]     = l_i[2 * i2]     * ax + rx;
            l_i[2 * i2 + 1] = l_i[2 * i2 + 1] * ay + ry;

            ull ap = pack2(ax, ay);
#pragma unroll
            for (int j = 0; j < 4; j++) o[i2][j].u = mul2(o[i2][j].u, ap);
        }

        __syncthreads();   // C: QK reads of Ktd done -> safe to overwrite with Pt

        // P -> transposed smem Pt[kcol][qrow]; row-pairs store as STS.64
#pragma unroll
        for (int i2 = 0; i2 < 4; i2++)
#pragma unroll
            for (int j = 0; j < 4; j++)
                *(ull*)&KtPt[(tx * 4 + j) * PROW + ty * 8 + 2 * i2] = acc[i2][j].u;

        __syncthreads();   // D: Pt visible

        // O += P @ V
#pragma unroll 8
        for (int k = 0; k < 64; k++) {
            ull pp[4];
#pragma unroll
            for (int i2 = 0; i2 < 4; i2++)
                pp[i2] = *(const ull*)&KtPt[k * PROW + ty * 8 + 2 * i2];
#pragma unroll
            for (int j = 0; j < 4; j++) {
                ull vd = *(const ull*)&Vsd[k * KROW + Bk + 2 * j];
#pragma unroll
                for (int i2 = 0; i2 < 4; i2++)
                    ffma2(o[i2][j].u, pp[i2], vd);
            }
        }
    }

    // epilogue: out[bh][r][c] = o / l  (two rows per i2)
#pragma unroll
    for (int i2 = 0; i2 < 4; i2++) {
        float invx = 1.f / l_i[2 * i2];
        float invy = 1.f / l_i[2 * i2 + 1];
        int r0 = q0 + ty * 8 + 2 * i2;
        float4 lo = make_float4(o[i2][0].f.x * invx, o[i2][1].f.x * invx,
                                o[i2][2].f.x * invx, o[i2][3].f.x * invx);
        float4 hi = make_float4(o[i2][0].f.y * invy, o[i2][1].f.y * invy,
                                o[i2][2].f.y * invy, o[i2][3].f.y * invy);
        *(float4*)&out[(bh * SEQ + r0)     * HDIM + tx * 4] = lo;
        *(float4*)&out[(bh * SEQ + r0 + 1) * HDIM + tx * 4] = hi;
    }
}

// ---------------------------------------------------------------------------
extern "C" void kernel_launch(void* const* d_in, const int* in_sizes, int n_in,
                              void* d_out, int out_size)
{
    const float* x    = (const float*)d_in[0];
    const float* W    = (const float*)d_in[1];
    const float* bias = (const float*)d_in[2];
    float* out        = (float*)d_out;

    const int smem = (64 * 128 + 64 * KROW + 64 * KROW) * sizeof(float); // 102400 B
    cudaFuncSetAttribute(attn_kernel, cudaFuncAttributeMaxDynamicSharedMemorySize, smem);

    qkv_gemm_kernel<<<dim3(768 / 64, 8192 / 128), 256>>>(x, W, bias);
    attn_kernel<<<dim3(SEQ / 128, BHTOT), 256, smem>>>(out);
}